// round 13
// baseline (speedup 1.0000x reference)
#include <cuda_runtime.h>
#include <cstdint>

#define BB 512
#define TT 1024
#define NN 64
#define NJOBS (2 * BB)          // recurrence jobs
#define NJOBS_ALL (NJOBS + BB)  // + score jobs

// Bidirectional split of the CRF forward chain + LPT scheduling + fused
// combine. R13: score computation peeled into 512 tail-of-queue jobs
// (critical warp never gathers); E = exp(trans) precomputed in the init
// kernel as pre-packed u64 arrays (jobs load 64 x LDG.64, no MUFU).
//   Forward  job: q_t = diag(exp x_t) * E^T q_{t-1},  t = 1..nf
//   Backward job: r_{k-1} = E * (exp(x_k) . r_k),      k = L-1..nf+1
//   Score    job: sc_b = masked unary + binary sums
//   log_norm = C_f + C_b + log(q_nf . r_nf);  out = sc - log_norm
// Combine runs in-place on the 3rd arrival per batch.

__device__ float              g_qf[BB][NN];
__device__ float              g_rb[BB][NN];
__device__ float              g_cf[BB];
__device__ float              g_cb[BB];
__device__ float              g_sc[BB];
__device__ unsigned           g_ctr;
__device__ unsigned           g_done[BB];
__device__ unsigned short     g_order[NJOBS_ALL];
// pre-packed E = exp(trans):
//   EFa[w][l] = (E[w][l],    E[w+32][l])      forward, cols l
//   EFb[w][l] = (E[w][l+32], E[w+32][l+32])   forward, cols l+32
//   EBa[w][l] = (E[l][w],    E[l][w+32])      backward, rows l
//   EBb[w][l] = (E[l+32][w], E[l+32][w+32])   backward, rows l+32
__device__ unsigned long long g_EFa[32][32], g_EFb[32][32];
__device__ unsigned long long g_EBa[32][32], g_EBb[32][32];

// ---- init: reset counters, rank jobs by length descending, build E ----
__global__ __launch_bounds__(NJOBS) void crf_init_kernel(
    const int*   __restrict__ lens,
    const float* __restrict__ trans)
{
    __shared__ unsigned hist[513];
    __shared__ unsigned ofs[513];
    __shared__ unsigned scan[NJOBS];
    const int tid = threadIdx.x;

    if (tid == 0) g_ctr = 0u;
    if (tid < BB) {
        g_done[tid] = 0u;
        g_order[NJOBS + tid] = (unsigned short)(NJOBS + tid);  // score jobs
    }
    if (tid < 513) { hist[tid] = 0u; ofs[tid] = 0u; }

    // E precompute: one entry per thread per array (w = tid>>5, l = tid&31)
    {
        const int w = tid >> 5;
        const int l = tid & 31;
        float a0 = __expf(trans[w * NN + l]);
        float a1 = __expf(trans[(w + 32) * NN + l]);
        unsigned long long pk;
        asm("mov.b64 %0, {%1,%2};" : "=l"(pk) : "f"(a0), "f"(a1));
        g_EFa[w][l] = pk;
        float b0 = __expf(trans[w * NN + l + 32]);
        float b1 = __expf(trans[(w + 32) * NN + l + 32]);
        asm("mov.b64 %0, {%1,%2};" : "=l"(pk) : "f"(b0), "f"(b1));
        g_EFb[w][l] = pk;
        float c0 = __expf(trans[l * NN + w]);
        float c1 = __expf(trans[l * NN + w + 32]);
        asm("mov.b64 %0, {%1,%2};" : "=l"(pk) : "f"(c0), "f"(c1));
        g_EBa[w][l] = pk;
        float d0 = __expf(trans[(l + 32) * NN + w]);
        float d1 = __expf(trans[(l + 32) * NN + w + 32]);
        asm("mov.b64 %0, {%1,%2};" : "=l"(pk) : "f"(d0), "f"(d1));
        g_EBb[w][l] = pk;
    }
    __syncthreads();

    const int b   = tid >> 1;
    const int dir = tid & 1;
    const int L   = lens[b];
    const int nf  = (L - 1) >> 1;
    const int len = dir ? (L - 1 - nf) : nf;   // 0..512
    atomicAdd(&hist[len], 1u);
    __syncthreads();

    scan[tid] = (tid <= 512) ? hist[512 - tid] : 0u;
    __syncthreads();
#pragma unroll
    for (int off = 1; off < NJOBS; off <<= 1) {
        unsigned v = (tid >= off) ? scan[tid - off] : 0u;
        __syncthreads();
        scan[tid] += v;
        __syncthreads();
    }

    const unsigned k     = (unsigned)(512 - len);
    const unsigned start = k ? scan[k - 1] : 0u;
    const unsigned pos   = start + atomicAdd(&ofs[len], 1u);
    g_order[pos] = (unsigned short)tid;
}

#define LOAD_CHUNK(dst, base)                                                 \
    do {                                                                      \
        asm volatile("ld.shared.v2.u64 {%0,%1}, [%2];"                        \
                     : "=l"(dst[0]), "=l"(dst[1]) : "r"(base));               \
        asm volatile("ld.shared.v2.u64 {%0,%1}, [%2];"                        \
                     : "=l"(dst[2]), "=l"(dst[3]) : "r"((base) + 16));        \
        asm volatile("ld.shared.v2.u64 {%0,%1}, [%2];"                        \
                     : "=l"(dst[4]), "=l"(dst[5]) : "r"((base) + 32));        \
        asm volatile("ld.shared.v2.u64 {%0,%1}, [%2];"                        \
                     : "=l"(dst[6]), "=l"(dst[7]) : "r"((base) + 48));        \
    } while (0)

#define FMA_CHUNK(g, vv)                                                      \
    do {                                                                      \
        _Pragma("unroll")                                                     \
        for (int k = 0; k < 8; k += 4) {                                      \
            asm("fma.rn.f32x2 %0, %1, %2, %0;" : "+l"(a0) : "l"(Ea[8*(g)+k])   , "l"(vv[k]));   \
            asm("fma.rn.f32x2 %0, %1, %2, %0;" : "+l"(b0) : "l"(Eb[8*(g)+k])   , "l"(vv[k]));   \
            asm("fma.rn.f32x2 %0, %1, %2, %0;" : "+l"(a1) : "l"(Ea[8*(g)+k+1]) , "l"(vv[k+1])); \
            asm("fma.rn.f32x2 %0, %1, %2, %0;" : "+l"(b1) : "l"(Eb[8*(g)+k+1]) , "l"(vv[k+1])); \
            asm("fma.rn.f32x2 %0, %1, %2, %0;" : "+l"(a2) : "l"(Ea[8*(g)+k+2]) , "l"(vv[k+2])); \
            asm("fma.rn.f32x2 %0, %1, %2, %0;" : "+l"(b2) : "l"(Eb[8*(g)+k+2]) , "l"(vv[k+2])); \
            asm("fma.rn.f32x2 %0, %1, %2, %0;" : "+l"(a3) : "l"(Ea[8*(g)+k+3]) , "l"(vv[k+3])); \
            asm("fma.rn.f32x2 %0, %1, %2, %0;" : "+l"(b3) : "l"(Eb[8*(g)+k+3]) , "l"(vv[k+3])); \
        }                                                                     \
    } while (0)

#define MATVEC_TAIL()                                                         \
    asm("add.rn.f32x2 %0, %0, %1;" : "+l"(a0) : "l"(a1));                     \
    asm("add.rn.f32x2 %0, %0, %1;" : "+l"(a2) : "l"(a3));                     \
    asm("add.rn.f32x2 %0, %0, %1;" : "+l"(b0) : "l"(b1));                     \
    asm("add.rn.f32x2 %0, %0, %1;" : "+l"(b2) : "l"(b3));                     \
    asm("add.rn.f32x2 %0, %0, %1;" : "+l"(a0) : "l"(a2));                     \
    asm("add.rn.f32x2 %0, %0, %1;" : "+l"(b0) : "l"(b2));                     \
    asm("mov.b64 {%0,%1}, %2;" : "=f"(gal), "=f"(gah) : "l"(a0));             \
    asm("mov.b64 {%0,%1}, %2;" : "=f"(gbl), "=f"(gbh) : "l"(b0));

#define MATVEC_NR(sbase)                                                      \
    unsigned long long v0[8], v1[8];                                          \
    LOAD_CHUNK(v0, sbase);                                                    \
    LOAD_CHUNK(v1, (sbase) + 64);                                             \
    unsigned long long a0 = 0ull, a1 = 0ull, a2 = 0ull, a3 = 0ull;            \
    unsigned long long b0 = 0ull, b1 = 0ull, b2 = 0ull, b3 = 0ull;            \
    float gal, gah, gbl, gbh;                                                 \
    FMA_CHUNK(0, v0);                                                         \
    LOAD_CHUNK(v0, (sbase) + 128);                                            \
    FMA_CHUNK(1, v1);                                                         \
    LOAD_CHUNK(v1, (sbase) + 192);                                            \
    FMA_CHUNK(2, v0);                                                         \
    FMA_CHUNK(3, v1);                                                         \
    MATVEC_TAIL()

#define MATVEC_RN(sbase)                                                      \
    unsigned long long v0[8], v1[8];                                          \
    LOAD_CHUNK(v0, sbase);                                                    \
    LOAD_CHUNK(v1, (sbase) + 64);                                             \
    unsigned q0bits;                                                          \
    asm("mov.b64 {%0,_}, %1;" : "=r"(q0bits) : "l"(v0[0]));                   \
    const int e = (int)((q0bits >> 23) & 0xff) - 127;                         \
    Ce += e;                                                                  \
    const float scale = __uint_as_float((unsigned)(127 - e) << 23);           \
    unsigned long long a0 = 0ull, a1 = 0ull, a2 = 0ull, a3 = 0ull;            \
    unsigned long long b0 = 0ull, b1 = 0ull, b2 = 0ull, b3 = 0ull;            \
    float gal, gah, gbl, gbh;                                                 \
    FMA_CHUNK(0, v0);                                                         \
    LOAD_CHUNK(v0, (sbase) + 128);                                            \
    FMA_CHUNK(1, v1);                                                         \
    LOAD_CHUNK(v1, (sbase) + 192);                                            \
    FMA_CHUNK(2, v0);                                                         \
    FMA_CHUNK(3, v1);                                                         \
    MATVEC_TAIL()

#define STS64P(addr, lo, hi)                                                  \
    do {                                                                      \
        unsigned long long _pk;                                               \
        asm("mov.b64 %0, {%1,%2};" : "=l"(_pk) : "f"(lo), "f"(hi));           \
        asm volatile("st.shared.b64 [%0], %1;" :: "r"(addr), "l"(_pk)         \
                     : "memory");                                             \
    } while (0)

#define FSTEP_NR(xva, xvb)                                                    \
    do {                                                                      \
        const float sxa = __expf(xva);                                        \
        const float sxb = __expf(xvb);                                        \
        MATVEC_NR(sw0);                                                       \
        qa = (gal + gah) * sxa;                                               \
        qb = (gbl + gbh) * sxb;                                               \
        STS64P(sst, qa, qb);                                                  \
    } while (0)

#define FSTEP_RN(xva, xvb)                                                    \
    do {                                                                      \
        const float sxa = __expf(xva);                                        \
        const float sxb = __expf(xvb);                                        \
        MATVEC_RN(sw0);                                                       \
        qa = (gal + gah) * (sxa * scale);                                     \
        qb = (gbl + gbh) * (sxb * scale);                                     \
        STS64P(sst, qa, qb);                                                  \
    } while (0)

#define BSTEP_NR(xva, xvb)                                                    \
    do {                                                                      \
        const float ua = __expf(xva) * ra;                                    \
        const float ub = __expf(xvb) * rb;                                    \
        STS64P(sst, ua, ub);                                                  \
        MATVEC_NR(sw0);                                                       \
        ra = gal + gah;                                                       \
        rb = gbl + gbh;                                                       \
    } while (0)

#define BSTEP_RN(xva, xvb)                                                    \
    do {                                                                      \
        const float ua = __expf(xva) * ra;                                    \
        const float ub = __expf(xvb) * rb;                                    \
        STS64P(sst, ua, ub);                                                  \
        MATVEC_RN(sw0);                                                       \
        ra = (gal + gah) * scale;                                             \
        rb = (gbl + gbh) * scale;                                             \
    } while (0)

__device__ __forceinline__ void crf_combine(int b, int lane,
                                            float* __restrict__ out)
{
    const float d0 = __ldcg(&g_qf[b][lane])      * __ldcg(&g_rb[b][lane]);
    const float d1 = __ldcg(&g_qf[b][lane + 32]) * __ldcg(&g_rb[b][lane + 32]);
    float d = d0 + d1;
#pragma unroll
    for (int o = 16; o; o >>= 1) d += __shfl_xor_sync(0xffffffffu, d, o);
    if (lane == 0) {
        const float log_norm = __ldcg(&g_cf[b]) + __ldcg(&g_cb[b]) + __logf(d);
        out[b] = __ldcg(&g_sc[b]) - log_norm;
    }
}

// arrive on g_done[b]; third arrival performs the combine
__device__ __forceinline__ void crf_arrive(int b, int lane,
                                           float* __restrict__ out)
{
    __threadfence();
    unsigned old = 0;
    if (lane == 0) old = atomicAdd(&g_done[b], 1u);
    old = __shfl_sync(0xffffffffu, old, 0);
    if (old == 2u) {
        __threadfence();
        crf_combine(b, lane, out);
    }
}

__global__ __launch_bounds__(128, 1) void crf_half_kernel(
    const float* __restrict__ inputs,   // [B, T, N]
    const float* __restrict__ trans,    // [N, N]
    const int*   __restrict__ tags,     // [B, T]
    const int*   __restrict__ lens,     // [B]
    float*       __restrict__ out)      // [B]
{
    const int lane = threadIdx.x & 31;
    const int wid  = threadIdx.x >> 5;

    __shared__ __align__(16) float pbuf[4][NN];

    for (;;) {
        unsigned j;
        if (lane == 0) j = atomicAdd(&g_ctr, 1u);
        j = __shfl_sync(0xffffffffu, j, 0);
        if (j >= NJOBS_ALL) return;
        j = g_order[j];                      // LPT order; scores at tail

        if (j >= NJOBS) {
            // ---------------- SCORE job ----------------------------------
            const int b = (int)(j - NJOBS);
            const int L = lens[b];
            const size_t tbase = (size_t)b * TT;
            float sc = 0.f;
            for (int t = lane; t < L; t += 32) {
                int tg = tags[tbase + t];
                sc += inputs[(tbase + t) * NN + tg];
                if (t >= 1) {
                    int tp = tags[tbase + t - 1];
                    sc += trans[tp * NN + tg];
                }
            }
#pragma unroll
            for (int o = 16; o; o >>= 1)
                sc += __shfl_xor_sync(0xffffffffu, sc, o);
            if (lane == 0) g_sc[b] = sc;
            crf_arrive(b, lane, out);
            continue;
        }

        const int b   = (int)(j >> 1);
        const int dir = (int)(j & 1);
        const int L   = lens[b];
        const int nf  = (L - 1) >> 1;
        const size_t tbase = (size_t)b * TT;
        const float* xp = inputs + tbase * NN;

        const unsigned sw0 =
            (unsigned)__cvta_generic_to_shared(&pbuf[wid][0]);
        const unsigned sst = sw0 + (unsigned)(lane * 8);

        if (dir == 0) {
            // ---------------- FORWARD half -------------------------------
            unsigned long long Ea[32], Eb[32];
#pragma unroll
            for (int w = 0; w < 32; ++w) {
                Ea[w] = g_EFa[w][lane];
                Eb[w] = g_EFb[w][lane];
            }

            float x0a = xp[lane];
            float x0b = xp[lane + 32];
            float M0  = __shfl_sync(0xffffffffu, x0a, 0);
            float qa  = __expf(x0a - M0);
            float qb  = __expf(x0b - M0);
            STS64P(sst, qa, qb);

            int Ce = 0;

            // preload x for t = 1..4 (rows <= 4 < TT, in-bounds)
            const float* xq = xp + NN;
            float xa0 = xq[lane],          xb0 = xq[lane + 32];
            float xa1 = xq[NN + lane],     xb1 = xq[NN + lane + 32];
            float xa2 = xq[2 * NN + lane], xb2 = xq[2 * NN + lane + 32];
            float xa3 = xq[3 * NN + lane], xb3 = xq[3 * NN + lane + 32];
            const float* xf = xp + 5 * NN;   // block-ahead pointer

            int t = 1;
            for (; t + 3 <= nf; t += 4) {
                const float ya0 = xf[lane],          yb0 = xf[lane + 32];
                const float ya1 = xf[NN + lane],     yb1 = xf[NN + lane + 32];
                const float ya2 = xf[2 * NN + lane], yb2 = xf[2 * NN + lane + 32];
                const float ya3 = xf[3 * NN + lane], yb3 = xf[3 * NN + lane + 32];

                FSTEP_NR(xa0, xb0);
                FSTEP_NR(xa1, xb1);
                FSTEP_NR(xa2, xb2);
                FSTEP_RN(xa3, xb3);

                xa0 = ya0; xb0 = yb0; xa1 = ya1; xb1 = yb1;
                xa2 = ya2; xb2 = yb2; xa3 = ya3; xb3 = yb3;
                xf += 4 * NN;
            }
            if (t     <= nf) { FSTEP_RN(xa0, xb0); }
            if (t + 1 <= nf) { FSTEP_RN(xa1, xb1); }
            if (t + 2 <= nf) { FSTEP_RN(xa2, xb2); }

            g_qf[b][lane]      = qa;
            g_qf[b][lane + 32] = qb;
            if (lane == 0)
                g_cf[b] = M0 + (float)Ce * 0.6931471805599453f;
        } else {
            // ---------------- BACKWARD half ------------------------------
            unsigned long long Ea[32], Eb[32];
#pragma unroll
            for (int w = 0; w < 32; ++w) {
                Ea[w] = g_EBa[w][lane];
                Eb[w] = g_EBb[w][lane];
            }

            const int nb = (L - 1) - nf;
            float ra = 1.f, rb = 1.f;
            int Ce = 0;

            // preload x for s = 0..3 (rows L-1-u, clamped >= 0)
            const int r0 = (L - 1) > 0 ? (L - 1) : 0;
            const int r1 = (L - 2) > 0 ? (L - 2) : 0;
            const int r2 = (L - 3) > 0 ? (L - 3) : 0;
            const int r3 = (L - 4) > 0 ? (L - 4) : 0;
            float xa0 = xp[r0 * NN + lane], xb0 = xp[r0 * NN + lane + 32];
            float xa1 = xp[r1 * NN + lane], xb1 = xp[r1 * NN + lane + 32];
            float xa2 = xp[r2 * NN + lane], xb2 = xp[r2 * NN + lane + 32];
            float xa3 = xp[r3 * NN + lane], xb3 = xp[r3 * NN + lane + 32];

            int kk = L - 5;   // row of next block's first prefetch
            int s = 0;
            for (; s + 3 < nb; s += 4) {
                const int c0 = kk     > 0 ? kk     : 0;
                const int c1 = kk - 1 > 0 ? kk - 1 : 0;
                const int c2 = kk - 2 > 0 ? kk - 2 : 0;
                const int c3 = kk - 3 > 0 ? kk - 3 : 0;
                const float ya0 = xp[c0 * NN + lane], yb0 = xp[c0 * NN + lane + 32];
                const float ya1 = xp[c1 * NN + lane], yb1 = xp[c1 * NN + lane + 32];
                const float ya2 = xp[c2 * NN + lane], yb2 = xp[c2 * NN + lane + 32];
                const float ya3 = xp[c3 * NN + lane], yb3 = xp[c3 * NN + lane + 32];

                BSTEP_NR(xa0, xb0);
                BSTEP_NR(xa1, xb1);
                BSTEP_NR(xa2, xb2);
                BSTEP_RN(xa3, xb3);

                xa0 = ya0; xb0 = yb0; xa1 = ya1; xb1 = yb1;
                xa2 = ya2; xb2 = yb2; xa3 = ya3; xb3 = yb3;
                kk -= 4;
            }
            if (s     < nb) { BSTEP_RN(xa0, xb0); }
            if (s + 1 < nb) { BSTEP_RN(xa1, xb1); }
            if (s + 2 < nb) { BSTEP_RN(xa2, xb2); }

            g_rb[b][lane]      = ra;
            g_rb[b][lane + 32] = rb;
            if (lane == 0)
                g_cb[b] = (float)Ce * 0.6931471805599453f;
        }

        crf_arrive(b, lane, out);
    }
}

extern "C" void kernel_launch(void* const* d_in, const int* in_sizes, int n_in,
                              void* d_out, int out_size)
{
    const float* inputs = (const float*)d_in[0];
    const float* trans  = (const float*)d_in[1];
    const int*   tags   = (const int*)d_in[2];
    const int*   lens   = (const int*)d_in[3];
    float*       out    = (float*)d_out;

    crf_init_kernel<<<1, NJOBS>>>(lens, trans);
    crf_half_kernel<<<148, 128>>>(inputs, trans, tags, lens, out);
}

// round 14
// speedup vs baseline: 1.0756x; 1.0756x over previous
#include <cuda_runtime.h>
#include <cstdint>

#define BB 512
#define TT 1024
#define NN 64
#define NJOBS (2 * BB)

// Bidirectional split of the CRF forward chain + LPT scheduling + fused
// combine (R12 structure: scores inline in the forward job, combine on 2nd
// arrival) + E = exp(trans) precomputed in the init kernel as pre-packed
// u64 tables (R13's one proven win; jobs load 64 x LDG.64, no MUFU).
//   Forward  job: q_t = diag(exp x_t) * E^T q_{t-1},  t = 1..nf  (+ scores)
//   Backward job: r_{k-1} = E * (exp(x_k) . r_k),      k = L-1..nf+1
//   log_norm = C_f + C_b + log(q_nf . r_nf);  out = sc - log_norm

__device__ float              g_qf[BB][NN];
__device__ float              g_rb[BB][NN];
__device__ float              g_cf[BB];
__device__ float              g_cb[BB];
__device__ float              g_sc[BB];
__device__ unsigned           g_ctr;
__device__ unsigned           g_done[BB];
__device__ unsigned short     g_order[NJOBS];
// pre-packed E = exp(trans):
//   EFa[w][l] = (E[w][l],    E[w+32][l])      forward, cols l
//   EFb[w][l] = (E[w][l+32], E[w+32][l+32])   forward, cols l+32
//   EBa[w][l] = (E[l][w],    E[l][w+32])      backward, rows l
//   EBb[w][l] = (E[l+32][w], E[l+32][w+32])   backward, rows l+32
__device__ unsigned long long g_EFa[32][32], g_EFb[32][32];
__device__ unsigned long long g_EBa[32][32], g_EBb[32][32];

// ---- init: reset counters, rank jobs by length descending, build E ----
__global__ __launch_bounds__(NJOBS) void crf_init_kernel(
    const int*   __restrict__ lens,
    const float* __restrict__ trans)
{
    __shared__ unsigned hist[513];
    __shared__ unsigned ofs[513];
    __shared__ unsigned scan[NJOBS];
    const int tid = threadIdx.x;

    if (tid == 0) g_ctr = 0u;
    if (tid < BB) g_done[tid] = 0u;
    if (tid < 513) { hist[tid] = 0u; ofs[tid] = 0u; }

    // E precompute: one entry per thread per table (w = tid>>5, l = tid&31)
    {
        const int w = tid >> 5;
        const int l = tid & 31;
        float a0 = __expf(trans[w * NN + l]);
        float a1 = __expf(trans[(w + 32) * NN + l]);
        unsigned long long pk;
        asm("mov.b64 %0, {%1,%2};" : "=l"(pk) : "f"(a0), "f"(a1));
        g_EFa[w][l] = pk;
        float b0 = __expf(trans[w * NN + l + 32]);
        float b1 = __expf(trans[(w + 32) * NN + l + 32]);
        asm("mov.b64 %0, {%1,%2};" : "=l"(pk) : "f"(b0), "f"(b1));
        g_EFb[w][l] = pk;
        float c0 = __expf(trans[l * NN + w]);
        float c1 = __expf(trans[l * NN + w + 32]);
        asm("mov.b64 %0, {%1,%2};" : "=l"(pk) : "f"(c0), "f"(c1));
        g_EBa[w][l] = pk;
        float d0 = __expf(trans[(l + 32) * NN + w]);
        float d1 = __expf(trans[(l + 32) * NN + w + 32]);
        asm("mov.b64 %0, {%1,%2};" : "=l"(pk) : "f"(d0), "f"(d1));
        g_EBb[w][l] = pk;
    }
    __syncthreads();

    const int b   = tid >> 1;
    const int dir = tid & 1;
    const int L   = lens[b];
    const int nf  = (L - 1) >> 1;
    const int len = dir ? (L - 1 - nf) : nf;   // 0..512
    atomicAdd(&hist[len], 1u);
    __syncthreads();

    scan[tid] = (tid <= 512) ? hist[512 - tid] : 0u;
    __syncthreads();
#pragma unroll
    for (int off = 1; off < NJOBS; off <<= 1) {
        unsigned v = (tid >= off) ? scan[tid - off] : 0u;
        __syncthreads();
        scan[tid] += v;
        __syncthreads();
    }

    const unsigned k     = (unsigned)(512 - len);
    const unsigned start = k ? scan[k - 1] : 0u;
    const unsigned pos   = start + atomicAdd(&ofs[len], 1u);
    g_order[pos] = (unsigned short)tid;
}

#define LOAD_CHUNK(dst, base)                                                 \
    do {                                                                      \
        asm volatile("ld.shared.v2.u64 {%0,%1}, [%2];"                        \
                     : "=l"(dst[0]), "=l"(dst[1]) : "r"(base));               \
        asm volatile("ld.shared.v2.u64 {%0,%1}, [%2];"                        \
                     : "=l"(dst[2]), "=l"(dst[3]) : "r"((base) + 16));        \
        asm volatile("ld.shared.v2.u64 {%0,%1}, [%2];"                        \
                     : "=l"(dst[4]), "=l"(dst[5]) : "r"((base) + 32));        \
        asm volatile("ld.shared.v2.u64 {%0,%1}, [%2];"                        \
                     : "=l"(dst[6]), "=l"(dst[7]) : "r"((base) + 48));        \
    } while (0)

#define FMA_CHUNK(g, vv)                                                      \
    do {                                                                      \
        _Pragma("unroll")                                                     \
        for (int k = 0; k < 8; k += 4) {                                      \
            asm("fma.rn.f32x2 %0, %1, %2, %0;" : "+l"(a0) : "l"(Ea[8*(g)+k])   , "l"(vv[k]));   \
            asm("fma.rn.f32x2 %0, %1, %2, %0;" : "+l"(b0) : "l"(Eb[8*(g)+k])   , "l"(vv[k]));   \
            asm("fma.rn.f32x2 %0, %1, %2, %0;" : "+l"(a1) : "l"(Ea[8*(g)+k+1]) , "l"(vv[k+1])); \
            asm("fma.rn.f32x2 %0, %1, %2, %0;" : "+l"(b1) : "l"(Eb[8*(g)+k+1]) , "l"(vv[k+1])); \
            asm("fma.rn.f32x2 %0, %1, %2, %0;" : "+l"(a2) : "l"(Ea[8*(g)+k+2]) , "l"(vv[k+2])); \
            asm("fma.rn.f32x2 %0, %1, %2, %0;" : "+l"(b2) : "l"(Eb[8*(g)+k+2]) , "l"(vv[k+2])); \
            asm("fma.rn.f32x2 %0, %1, %2, %0;" : "+l"(a3) : "l"(Ea[8*(g)+k+3]) , "l"(vv[k+3])); \
            asm("fma.rn.f32x2 %0, %1, %2, %0;" : "+l"(b3) : "l"(Eb[8*(g)+k+3]) , "l"(vv[k+3])); \
        }                                                                     \
    } while (0)

#define MATVEC_TAIL()                                                         \
    asm("add.rn.f32x2 %0, %0, %1;" : "+l"(a0) : "l"(a1));                     \
    asm("add.rn.f32x2 %0, %0, %1;" : "+l"(a2) : "l"(a3));                     \
    asm("add.rn.f32x2 %0, %0, %1;" : "+l"(b0) : "l"(b1));                     \
    asm("add.rn.f32x2 %0, %0, %1;" : "+l"(b2) : "l"(b3));                     \
    asm("add.rn.f32x2 %0, %0, %1;" : "+l"(a0) : "l"(a2));                     \
    asm("add.rn.f32x2 %0, %0, %1;" : "+l"(b0) : "l"(b2));                     \
    asm("mov.b64 {%0,%1}, %2;" : "=f"(gal), "=f"(gah) : "l"(a0));             \
    asm("mov.b64 {%0,%1}, %2;" : "=f"(gbl), "=f"(gbh) : "l"(b0));

#define MATVEC_NR(sbase)                                                      \
    unsigned long long v0[8], v1[8];                                          \
    LOAD_CHUNK(v0, sbase);                                                    \
    LOAD_CHUNK(v1, (sbase) + 64);                                             \
    unsigned long long a0 = 0ull, a1 = 0ull, a2 = 0ull, a3 = 0ull;            \
    unsigned long long b0 = 0ull, b1 = 0ull, b2 = 0ull, b3 = 0ull;            \
    float gal, gah, gbl, gbh;                                                 \
    FMA_CHUNK(0, v0);                                                         \
    LOAD_CHUNK(v0, (sbase) + 128);                                            \
    FMA_CHUNK(1, v1);                                                         \
    LOAD_CHUNK(v1, (sbase) + 192);                                            \
    FMA_CHUNK(2, v0);                                                         \
    FMA_CHUNK(3, v1);                                                         \
    MATVEC_TAIL()

#define MATVEC_RN(sbase)                                                      \
    unsigned long long v0[8], v1[8];                                          \
    LOAD_CHUNK(v0, sbase);                                                    \
    LOAD_CHUNK(v1, (sbase) + 64);                                             \
    unsigned q0bits;                                                          \
    asm("mov.b64 {%0,_}, %1;" : "=r"(q0bits) : "l"(v0[0]));                   \
    const int e = (int)((q0bits >> 23) & 0xff) - 127;                         \
    Ce += e;                                                                  \
    const float scale = __uint_as_float((unsigned)(127 - e) << 23);           \
    unsigned long long a0 = 0ull, a1 = 0ull, a2 = 0ull, a3 = 0ull;            \
    unsigned long long b0 = 0ull, b1 = 0ull, b2 = 0ull, b3 = 0ull;            \
    float gal, gah, gbl, gbh;                                                 \
    FMA_CHUNK(0, v0);                                                         \
    LOAD_CHUNK(v0, (sbase) + 128);                                            \
    FMA_CHUNK(1, v1);                                                         \
    LOAD_CHUNK(v1, (sbase) + 192);                                            \
    FMA_CHUNK(2, v0);                                                         \
    FMA_CHUNK(3, v1);                                                         \
    MATVEC_TAIL()

#define STS64P(addr, lo, hi)                                                  \
    do {                                                                      \
        unsigned long long _pk;                                               \
        asm("mov.b64 %0, {%1,%2};" : "=l"(_pk) : "f"(lo), "f"(hi));           \
        asm volatile("st.shared.b64 [%0], %1;" :: "r"(addr), "l"(_pk)         \
                     : "memory");                                             \
    } while (0)

#define FSTEP_NR(xva, xvb)                                                    \
    do {                                                                      \
        const float sxa = __expf(xva);                                        \
        const float sxb = __expf(xvb);                                        \
        MATVEC_NR(sw0);                                                       \
        qa = (gal + gah) * sxa;                                               \
        qb = (gbl + gbh) * sxb;                                               \
        STS64P(sst, qa, qb);                                                  \
    } while (0)

#define FSTEP_RN(xva, xvb)                                                    \
    do {                                                                      \
        const float sxa = __expf(xva);                                        \
        const float sxb = __expf(xvb);                                        \
        MATVEC_RN(sw0);                                                       \
        qa = (gal + gah) * (sxa * scale);                                     \
        qb = (gbl + gbh) * (sxb * scale);                                     \
        STS64P(sst, qa, qb);                                                  \
    } while (0)

#define BSTEP_NR(xva, xvb)                                                    \
    do {                                                                      \
        const float ua = __expf(xva) * ra;                                    \
        const float ub = __expf(xvb) * rb;                                    \
        STS64P(sst, ua, ub);                                                  \
        MATVEC_NR(sw0);                                                       \
        ra = gal + gah;                                                       \
        rb = gbl + gbh;                                                       \
    } while (0)

#define BSTEP_RN(xva, xvb)                                                    \
    do {                                                                      \
        const float ua = __expf(xva) * ra;                                    \
        const float ub = __expf(xvb) * rb;                                    \
        STS64P(sst, ua, ub);                                                  \
        MATVEC_RN(sw0);                                                       \
        ra = (gal + gah) * scale;                                             \
        rb = (gbl + gbh) * scale;                                             \
    } while (0)

__device__ __forceinline__ void crf_combine(int b, int lane,
                                            float* __restrict__ out)
{
    const float d0 = __ldcg(&g_qf[b][lane])      * __ldcg(&g_rb[b][lane]);
    const float d1 = __ldcg(&g_qf[b][lane + 32]) * __ldcg(&g_rb[b][lane + 32]);
    float d = d0 + d1;
#pragma unroll
    for (int o = 16; o; o >>= 1) d += __shfl_xor_sync(0xffffffffu, d, o);
    if (lane == 0) {
        const float log_norm = __ldcg(&g_cf[b]) + __ldcg(&g_cb[b]) + __logf(d);
        out[b] = __ldcg(&g_sc[b]) - log_norm;
    }
}

__global__ __launch_bounds__(128, 1) void crf_half_kernel(
    const float* __restrict__ inputs,   // [B, T, N]
    const float* __restrict__ trans,    // [N, N]
    const int*   __restrict__ tags,     // [B, T]
    const int*   __restrict__ lens,     // [B]
    float*       __restrict__ out)      // [B]
{
    const int lane = threadIdx.x & 31;
    const int wid  = threadIdx.x >> 5;

    __shared__ __align__(16) float pbuf[4][NN];

    for (;;) {
        unsigned j;
        if (lane == 0) j = atomicAdd(&g_ctr, 1u);
        j = __shfl_sync(0xffffffffu, j, 0);
        if (j >= NJOBS) return;
        j = g_order[j];                      // LPT order

        const int b   = (int)(j >> 1);
        const int dir = (int)(j & 1);
        const int L   = lens[b];
        const int nf  = (L - 1) >> 1;
        const size_t tbase = (size_t)b * TT;
        const float* xp = inputs + tbase * NN;

        const unsigned sw0 =
            (unsigned)__cvta_generic_to_shared(&pbuf[wid][0]);
        const unsigned sst = sw0 + (unsigned)(lane * 8);

        if (dir == 0) {
            // ---------------- FORWARD half + scores ----------------------
            float sc = 0.f;
            for (int t = lane; t < L; t += 32) {
                int tg = tags[tbase + t];
                sc += inputs[(tbase + t) * NN + tg];
                if (t >= 1) {
                    int tp = tags[tbase + t - 1];
                    sc += trans[tp * NN + tg];
                }
            }
#pragma unroll
            for (int o = 16; o; o >>= 1)
                sc += __shfl_xor_sync(0xffffffffu, sc, o);

            unsigned long long Ea[32], Eb[32];
#pragma unroll
            for (int w = 0; w < 32; ++w) {
                Ea[w] = g_EFa[w][lane];
                Eb[w] = g_EFb[w][lane];
            }

            float x0a = xp[lane];
            float x0b = xp[lane + 32];
            float M0  = __shfl_sync(0xffffffffu, x0a, 0);
            float qa  = __expf(x0a - M0);
            float qb  = __expf(x0b - M0);
            STS64P(sst, qa, qb);

            int Ce = 0;

            // preload x for t = 1..4 (rows <= 4 < TT, in-bounds)
            const float* xq = xp + NN;
            float xa0 = xq[lane],          xb0 = xq[lane + 32];
            float xa1 = xq[NN + lane],     xb1 = xq[NN + lane + 32];
            float xa2 = xq[2 * NN + lane], xb2 = xq[2 * NN + lane + 32];
            float xa3 = xq[3 * NN + lane], xb3 = xq[3 * NN + lane + 32];
            const float* xf = xp + 5 * NN;   // block-ahead pointer

            int t = 1;
            for (; t + 3 <= nf; t += 4) {
                const float ya0 = xf[lane],          yb0 = xf[lane + 32];
                const float ya1 = xf[NN + lane],     yb1 = xf[NN + lane + 32];
                const float ya2 = xf[2 * NN + lane], yb2 = xf[2 * NN + lane + 32];
                const float ya3 = xf[3 * NN + lane], yb3 = xf[3 * NN + lane + 32];

                FSTEP_NR(xa0, xb0);
                FSTEP_NR(xa1, xb1);
                FSTEP_NR(xa2, xb2);
                FSTEP_RN(xa3, xb3);

                xa0 = ya0; xb0 = yb0; xa1 = ya1; xb1 = yb1;
                xa2 = ya2; xb2 = yb2; xa3 = ya3; xb3 = yb3;
                xf += 4 * NN;
            }
            if (t     <= nf) { FSTEP_RN(xa0, xb0); }
            if (t + 1 <= nf) { FSTEP_RN(xa1, xb1); }
            if (t + 2 <= nf) { FSTEP_RN(xa2, xb2); }

            g_qf[b][lane]      = qa;
            g_qf[b][lane + 32] = qb;
            if (lane == 0) {
                g_cf[b] = M0 + (float)Ce * 0.6931471805599453f;
                g_sc[b] = sc;
            }
        } else {
            // ---------------- BACKWARD half ------------------------------
            unsigned long long Ea[32], Eb[32];
#pragma unroll
            for (int w = 0; w < 32; ++w) {
                Ea[w] = g_EBa[w][lane];
                Eb[w] = g_EBb[w][lane];
            }

            const int nb = (L - 1) - nf;
            float ra = 1.f, rb = 1.f;
            int Ce = 0;

            // preload x for s = 0..3 (rows L-1-u, clamped >= 0)
            const int r0 = (L - 1) > 0 ? (L - 1) : 0;
            const int r1 = (L - 2) > 0 ? (L - 2) : 0;
            const int r2 = (L - 3) > 0 ? (L - 3) : 0;
            const int r3 = (L - 4) > 0 ? (L - 4) : 0;
            float xa0 = xp[r0 * NN + lane], xb0 = xp[r0 * NN + lane + 32];
            float xa1 = xp[r1 * NN + lane], xb1 = xp[r1 * NN + lane + 32];
            float xa2 = xp[r2 * NN + lane], xb2 = xp[r2 * NN + lane + 32];
            float xa3 = xp[r3 * NN + lane], xb3 = xp[r3 * NN + lane + 32];

            int kk = L - 5;   // row of next block's first prefetch
            int s = 0;
            for (; s + 3 < nb; s += 4) {
                const int c0 = kk     > 0 ? kk     : 0;
                const int c1 = kk - 1 > 0 ? kk - 1 : 0;
                const int c2 = kk - 2 > 0 ? kk - 2 : 0;
                const int c3 = kk - 3 > 0 ? kk - 3 : 0;
                const float ya0 = xp[c0 * NN + lane], yb0 = xp[c0 * NN + lane + 32];
                const float ya1 = xp[c1 * NN + lane], yb1 = xp[c1 * NN + lane + 32];
                const float ya2 = xp[c2 * NN + lane], yb2 = xp[c2 * NN + lane + 32];
                const float ya3 = xp[c3 * NN + lane], yb3 = xp[c3 * NN + lane + 32];

                BSTEP_NR(xa0, xb0);
                BSTEP_NR(xa1, xb1);
                BSTEP_NR(xa2, xb2);
                BSTEP_RN(xa3, xb3);

                xa0 = ya0; xb0 = yb0; xa1 = ya1; xb1 = yb1;
                xa2 = ya2; xb2 = yb2; xa3 = ya3; xb3 = yb3;
                kk -= 4;
            }
            if (s     < nb) { BSTEP_RN(xa0, xb0); }
            if (s + 1 < nb) { BSTEP_RN(xa1, xb1); }
            if (s + 2 < nb) { BSTEP_RN(xa2, xb2); }

            g_rb[b][lane]      = ra;
            g_rb[b][lane + 32] = rb;
            if (lane == 0)
                g_cb[b] = (float)Ce * 0.6931471805599453f;
        }

        // ---- completion: second finisher combines ----
        __threadfence();
        unsigned old = 0;
        if (lane == 0) old = atomicAdd(&g_done[b], 1u);
        old = __shfl_sync(0xffffffffu, old, 0);
        if (old == 1u) {
            __threadfence();
            crf_combine(b, lane, out);
        }
    }
}

extern "C" void kernel_launch(void* const* d_in, const int* in_sizes, int n_in,
                              void* d_out, int out_size)
{
    const float* inputs = (const float*)d_in[0];
    const float* trans  = (const float*)d_in[1];
    const int*   tags   = (const int*)d_in[2];
    const int*   lens   = (const int*)d_in[3];
    float*       out    = (float*)d_out;

    crf_init_kernel<<<1, NJOBS>>>(lens, trans);
    crf_half_kernel<<<148, 128>>>(inputs, trans, tags, lens, out);
}